// round 9
// baseline (speedup 1.0000x reference)
#include <cuda_runtime.h>

// REINFORCE fused kernel, GB300 sm_103a — R8
//
// out[0:T)      = generator_objective
// out[T:T+B*T)  = cumulative_rewards (row-major [B,T])
//
// 3 kernels:
//   phaseA      : per-row reverse discounted suffix scan (4 elems/thread,
//                 TPB=512, 1-row prefetch), writes cum + per-block partial
//                 colsum(cum - base). Block 0 also zeroes out[0:T).
//   reduce_mean : 64 blocks x 16 warps, coalesced partial reduction -> g_mean
//                 (g_partA is L2-hot from phaseA).
//   phaseB      : centered clipped advantage * log_probs; REDG atomicAdd of
//                 per-block column partials directly into out[0:T).
//                 Row order REVERSED vs phaseA so cum/base hit L2.

namespace {
constexpr int   Bn     = 4096;
constexpr int   Tn     = 2048;
constexpr float GAMMA  = 0.99f;
constexpr float CLIPV  = 5.0f;
constexpr int   TPB    = 512;    // thread k owns cols [4k, 4k+4)
constexpr int   ROWS_A = 8;      // rows per block, phase A
constexpr int   ROWS_B = 16;     // rows per block, phase B
constexpr int   NPA    = Bn / ROWS_A;   // 512 phase-A blocks
constexpr int   NPB    = Bn / ROWS_B;   // 256 phase-B blocks
constexpr int   NWARP  = TPB / 32;      // 16
}

__device__ float g_partA[NPA][Tn];   // per-block partial colsum(cum - base)
__device__ float g_mean[Tn];         // batch mean of (cum - base)

__device__ __forceinline__ float log_sigmoid(float x) {
    float t = __expf(-fabsf(x));
    return fminf(x, 0.f) - __logf(1.f + t);
}

__global__ __launch_bounds__(TPB) void phaseA_kernel(
    const float* __restrict__ logits,
    const float* __restrict__ weight,
    const float* __restrict__ base,
    float* __restrict__ cumout,
    float* __restrict__ obj)
{
    __shared__ float Wsh[2][NWARP];

    const int tid  = threadIdx.x;
    const int lane = tid & 31;
    const int warp = tid >> 5;
    const int col0 = tid * 4;
    const int row0 = blockIdx.x * ROWS_A;

    // block 0 zeroes the objective accumulator for phaseB's atomics
    if (blockIdx.x == 0)
        *(float4*)(obj + col0) = make_float4(0.f, 0.f, 0.f, 0.f);

    // gamma powers
    const float g1 = GAMMA;
    const float g2 = g1 * g1;
    const float g3 = g2 * g1;
    const float g4 = g2 * g2;          // chunk ratio
    const float w1  = g4;
    const float w2  = w1 * w1;         // gamma^8
    const float w4  = w2 * w2;         // gamma^16
    const float w8  = w4 * w4;         // gamma^32
    const float w16 = w8 * w8;         // gamma^64
    const float r128 = w16 * w16;      // warp ratio gamma^128

    // (gamma^4)^(31-lane)
    float r4p31 = 1.f;
    for (int i = 0; i < 31 - lane; i++) r4p31 *= g4;

    float d0 = 0.f, d1 = 0.f, d2 = 0.f, d3 = 0.f;

    long off = (long)row0 * Tn + col0;

    // prefetch row 0
    float4 lv = __ldcs((const float4*)(logits + off));
    float4 wv = __ldcs((const float4*)(weight + off));
    float4 bv = *(const float4*)(base + off);

    #pragma unroll
    for (int r = 0; r < ROWS_A; ++r) {
        const float4 l = lv, w = wv, b = bv;
        const long offc = off;
        if (r + 1 < ROWS_A) {
            off += Tn;
            lv = __ldcs((const float4*)(logits + off));
            wv = __ldcs((const float4*)(weight + off));
            bv = *(const float4*)(base + off);
        }

        // weighted rewards + local reverse suffix (chunk of 4)
        const float ls3 = w.w * log_sigmoid(l.w);
        const float ls2 = w.z * log_sigmoid(l.z) + g1 * ls3;
        const float ls1 = w.y * log_sigmoid(l.y) + g1 * ls2;
        const float ls0 = w.x * log_sigmoid(l.x) + g1 * ls1;

        // warp inclusive suffix scan over chunk heads, ratio gamma^4
        float v = ls0;
        float o;
        o = __shfl_down_sync(0xffffffffu, v, 1);  if (lane < 31) v += w1  * o;
        o = __shfl_down_sync(0xffffffffu, v, 2);  if (lane < 30) v += w2  * o;
        o = __shfl_down_sync(0xffffffffu, v, 4);  if (lane < 28) v += w4  * o;
        o = __shfl_down_sync(0xffffffffu, v, 8);  if (lane < 24) v += w8  * o;
        o = __shfl_down_sync(0xffffffffu, v, 16); if (lane < 16) v += w16 * o;
        float vn = __shfl_down_sync(0xffffffffu, v, 1);
        if (lane == 31) vn = 0.f;

        const int par = r & 1;
        if (lane == 0) Wsh[par][warp] = v;   // warp-span cum at warp start
        __syncthreads();                     // 1 barrier/row; parity = WAR safe

        // inclusive suffix over later warps, ratio gamma^128
        float swn = 0.f;
        #pragma unroll
        for (int u = NWARP - 1; u >= 1; --u)
            if (u > warp) swn = Wsh[par][u] + r128 * swn;

        // carry = full cum at col0+4
        const float C = vn + r4p31 * swn;

        const float c0 = ls0 + g4 * C;
        const float c1 = ls1 + g3 * C;
        const float c2 = ls2 + g2 * C;
        const float c3 = ls3 + g1 * C;

        *(float4*)(cumout + offc) = make_float4(c0, c1, c2, c3);

        d0 += c0 - b.x;
        d1 += c1 - b.y;
        d2 += c2 - b.z;
        d3 += c3 - b.w;
    }

    *(float4*)(&g_partA[blockIdx.x][col0]) = make_float4(d0, d1, d2, d3);
}

// 64 blocks x 512 threads. Block owns 32 columns; warp w sums partials
// p = w, w+16, ... (coalesced 128B rows), cross-warp combine in padded smem.
__global__ __launch_bounds__(512) void reduce_mean_kernel() {
    __shared__ float sh[16][33];
    const int lane = threadIdx.x & 31;
    const int w    = threadIdx.x >> 5;
    const int col  = blockIdx.x * 32 + lane;

    float s = 0.f;
    #pragma unroll 8
    for (int p = w; p < NPA; p += 16)
        s += g_partA[p][col];
    sh[w][lane] = s;
    __syncthreads();

    if (w == 0) {
        float t = 0.f;
        #pragma unroll
        for (int u = 0; u < 16; ++u) t += sh[u][lane];
        g_mean[col] = t * (1.f / Bn);
    }
}

__global__ __launch_bounds__(TPB) void phaseB_kernel(
    const float* __restrict__ cum,
    const float* __restrict__ base,
    const float* __restrict__ logp,
    float* __restrict__ obj)
{
    const int tid  = threadIdx.x;
    const int col0 = tid * 4;
    // REVERSED row order: start with rows phaseA wrote last (L2-resident)
    const int row0 = (NPB - 1 - blockIdx.x) * ROWS_B;

    const float4 m = *(const float4*)(g_mean + col0);

    float o0 = 0.f, o1 = 0.f, o2 = 0.f, o3 = 0.f;

    long off = (long)row0 * Tn + col0;

    // prefetch row 0
    float4 cv = __ldcs((const float4*)(cum + off));
    float4 bv = __ldcs((const float4*)(base + off));
    float4 pv = __ldcs((const float4*)(logp + off));

    #pragma unroll 4
    for (int r = 0; r < ROWS_B; ++r) {
        const float4 c = cv, b = bv, p = pv;
        if (r + 1 < ROWS_B) {
            off += Tn;
            cv = __ldcs((const float4*)(cum + off));
            bv = __ldcs((const float4*)(base + off));
            pv = __ldcs((const float4*)(logp + off));
        }

        float a0 = c.x - b.x - m.x;
        float a1 = c.y - b.y - m.y;
        float a2 = c.z - b.z - m.z;
        float a3 = c.w - b.w - m.w;
        a0 = fminf(fmaxf(a0, -CLIPV), CLIPV);
        a1 = fminf(fmaxf(a1, -CLIPV), CLIPV);
        a2 = fminf(fmaxf(a2, -CLIPV), CLIPV);
        a3 = fminf(fmaxf(a3, -CLIPV), CLIPV);

        o0 += a0 * p.x;
        o1 += a1 * p.y;
        o2 += a2 * p.z;
        o3 += a3 * p.w;
    }

    // direct column reduction into the output (REDG, no return value)
    atomicAdd(&obj[col0 + 0], o0);
    atomicAdd(&obj[col0 + 1], o1);
    atomicAdd(&obj[col0 + 2], o2);
    atomicAdd(&obj[col0 + 3], o3);
}

extern "C" void kernel_launch(void* const* d_in, const int* in_sizes, int n_in,
                              void* d_out, int out_size) {
    const float* logp   = (const float*)d_in[0];  // log_probs  [B,T]
    const float* logits = (const float*)d_in[1];  // logits     [B,T,1]
    const float* weight = (const float*)d_in[2];  // weight     [B,T]
    const float* base   = (const float*)d_in[3];  // baselines  [B,T,1]
    float* out = (float*)d_out;

    phaseA_kernel<<<NPA, TPB>>>(logits, weight, base, out + Tn, out);
    reduce_mean_kernel<<<Tn / 32, 512>>>();
    phaseB_kernel<<<NPB, TPB>>>(out + Tn, base, logp, out);
}

// round 11
// speedup vs baseline: 1.4416x; 1.4416x over previous
#include <cuda_runtime.h>

// REINFORCE fused kernel, GB300 sm_103a — R9
//
// out[0:T)      = generator_objective
// out[T:T+B*T)  = cumulative_rewards (row-major [B,T])
//
// 3 kernels:
//   phaseA      : per-row reverse discounted suffix scan. TPB=512 (4 cols/thr),
//                 ROWS_A=16, grid=256 -> single wave at occupancy 2
//                 (__launch_bounds__(512,2) forces regs<=64 -> 32 warps/SM).
//                 Writes cum + per-block partial colsum(cum-base).
//                 Block 0 zeroes out[0:T).
//   reduce_mean : 64 blocks x 16 warps, coalesced partial reduction -> g_mean.
//   phaseB      : centered clipped advantage * log_probs; per-block column
//                 partials added straight into out[0:T) via REDG atomics.
//                 cum/base default-cached (L2 hits on phaseA's writes),
//                 logp streamed evict-first.

namespace {
constexpr int   Bn     = 4096;
constexpr int   Tn     = 2048;
constexpr float GAMMA  = 0.99f;
constexpr float CLIPV  = 5.0f;
constexpr int   TPB    = 512;    // thread k owns cols [4k, 4k+4)
constexpr int   ROWS_A = 16;     // rows per block, phase A
constexpr int   ROWS_B = 16;     // rows per block, phase B
constexpr int   NPA    = Bn / ROWS_A;   // 256 phase-A blocks (single wave @ occ2)
constexpr int   NPB    = Bn / ROWS_B;   // 256 phase-B blocks
constexpr int   NWARP  = TPB / 32;      // 16
}

__device__ float g_partA[NPA][Tn];   // per-block partial colsum(cum - base)
__device__ float g_mean[Tn];         // batch mean of (cum - base)

__device__ __forceinline__ float log_sigmoid(float x) {
    float t = __expf(-fabsf(x));
    return fminf(x, 0.f) - __logf(1.f + t);
}

__global__ __launch_bounds__(TPB, 2) void phaseA_kernel(
    const float* __restrict__ logits,
    const float* __restrict__ weight,
    const float* __restrict__ base,
    float* __restrict__ cumout,
    float* __restrict__ obj)
{
    __shared__ float Wsh[2][NWARP];

    const int tid  = threadIdx.x;
    const int lane = tid & 31;
    const int warp = tid >> 5;
    const int col0 = tid * 4;
    const int row0 = blockIdx.x * ROWS_A;

    // block 0 zeroes the objective accumulator for phaseB's atomics
    if (blockIdx.x == 0)
        *(float4*)(obj + col0) = make_float4(0.f, 0.f, 0.f, 0.f);

    // gamma powers
    const float g1 = GAMMA;
    const float g2 = g1 * g1;
    const float g3 = g2 * g1;
    const float g4 = g2 * g2;          // chunk ratio
    const float w1  = g4;
    const float w2  = w1 * w1;         // gamma^8
    const float w4  = w2 * w2;         // gamma^16
    const float w8  = w4 * w4;         // gamma^32
    const float w16 = w8 * w8;         // gamma^64
    const float r128 = w16 * w16;      // warp ratio gamma^128

    // (gamma^4)^(31-lane) via one MUFU: log2(0.99^4) = -0.057998278
    const float r4p31 = exp2f((float)(31 - lane) * -0.05799828f);

    float d0 = 0.f, d1 = 0.f, d2 = 0.f, d3 = 0.f;

    long off = (long)row0 * Tn + col0;

    // prefetch row 0
    float4 lv = __ldcs((const float4*)(logits + off));
    float4 wv = __ldcs((const float4*)(weight + off));
    float4 bv = *(const float4*)(base + off);

    #pragma unroll
    for (int r = 0; r < ROWS_A; ++r) {
        const float4 l = lv, w = wv, b = bv;
        const long offc = off;
        if (r + 1 < ROWS_A) {
            off += Tn;
            lv = __ldcs((const float4*)(logits + off));
            wv = __ldcs((const float4*)(weight + off));
            bv = *(const float4*)(base + off);
        }

        // weighted rewards + local reverse suffix (chunk of 4)
        const float ls3 = w.w * log_sigmoid(l.w);
        const float ls2 = w.z * log_sigmoid(l.z) + g1 * ls3;
        const float ls1 = w.y * log_sigmoid(l.y) + g1 * ls2;
        const float ls0 = w.x * log_sigmoid(l.x) + g1 * ls1;

        // warp inclusive suffix scan over chunk heads, ratio gamma^4
        float v = ls0;
        float o;
        o = __shfl_down_sync(0xffffffffu, v, 1);  if (lane < 31) v += w1  * o;
        o = __shfl_down_sync(0xffffffffu, v, 2);  if (lane < 30) v += w2  * o;
        o = __shfl_down_sync(0xffffffffu, v, 4);  if (lane < 28) v += w4  * o;
        o = __shfl_down_sync(0xffffffffu, v, 8);  if (lane < 24) v += w8  * o;
        o = __shfl_down_sync(0xffffffffu, v, 16); if (lane < 16) v += w16 * o;
        float vn = __shfl_down_sync(0xffffffffu, v, 1);
        if (lane == 31) vn = 0.f;

        const int par = r & 1;
        if (lane == 0) Wsh[par][warp] = v;   // warp-span cum at warp start
        __syncthreads();                     // 1 barrier/row; parity = WAR safe

        // inclusive suffix over later warps, ratio gamma^128
        float swn = 0.f;
        #pragma unroll
        for (int u = NWARP - 1; u >= 1; --u)
            if (u > warp) swn = Wsh[par][u] + r128 * swn;

        // carry = full cum at col0+4
        const float C = vn + r4p31 * swn;

        const float c0 = ls0 + g4 * C;
        const float c1 = ls1 + g3 * C;
        const float c2 = ls2 + g2 * C;
        const float c3 = ls3 + g1 * C;

        *(float4*)(cumout + offc) = make_float4(c0, c1, c2, c3);

        d0 += c0 - b.x;
        d1 += c1 - b.y;
        d2 += c2 - b.z;
        d3 += c3 - b.w;
    }

    *(float4*)(&g_partA[blockIdx.x][col0]) = make_float4(d0, d1, d2, d3);
}

// 64 blocks x 512 threads. Block owns 32 columns; warp w sums partials
// p = w, w+16, ... (coalesced 128B rows), cross-warp combine in padded smem.
__global__ __launch_bounds__(512) void reduce_mean_kernel() {
    __shared__ float sh[16][33];
    const int lane = threadIdx.x & 31;
    const int w    = threadIdx.x >> 5;
    const int col  = blockIdx.x * 32 + lane;

    float s = 0.f;
    #pragma unroll 8
    for (int p = w; p < NPA; p += 16)
        s += g_partA[p][col];
    sh[w][lane] = s;
    __syncthreads();

    if (w == 0) {
        float t = 0.f;
        #pragma unroll
        for (int u = 0; u < 16; ++u) t += sh[u][lane];
        g_mean[col] = t * (1.f / Bn);
    }
}

__global__ __launch_bounds__(TPB) void phaseB_kernel(
    const float* __restrict__ cum,
    const float* __restrict__ base,
    const float* __restrict__ logp,
    float* __restrict__ obj)
{
    const int tid  = threadIdx.x;
    const int col0 = tid * 4;
    const int row0 = blockIdx.x * ROWS_B;

    const float4 m = *(const float4*)(g_mean + col0);

    float o0 = 0.f, o1 = 0.f, o2 = 0.f, o3 = 0.f;

    long off = (long)row0 * Tn + col0;

    // prefetch row 0; cum/base default-cached (L2-resident from phaseA)
    float4 cv = *(const float4*)(cum + off);
    float4 bv = *(const float4*)(base + off);
    float4 pv = __ldcs((const float4*)(logp + off));

    #pragma unroll 4
    for (int r = 0; r < ROWS_B; ++r) {
        const float4 c = cv, b = bv, p = pv;
        if (r + 1 < ROWS_B) {
            off += Tn;
            cv = *(const float4*)(cum + off);
            bv = *(const float4*)(base + off);
            pv = __ldcs((const float4*)(logp + off));
        }

        float a0 = c.x - b.x - m.x;
        float a1 = c.y - b.y - m.y;
        float a2 = c.z - b.z - m.z;
        float a3 = c.w - b.w - m.w;
        a0 = fminf(fmaxf(a0, -CLIPV), CLIPV);
        a1 = fminf(fmaxf(a1, -CLIPV), CLIPV);
        a2 = fminf(fmaxf(a2, -CLIPV), CLIPV);
        a3 = fminf(fmaxf(a3, -CLIPV), CLIPV);

        o0 += a0 * p.x;
        o1 += a1 * p.y;
        o2 += a2 * p.z;
        o3 += a3 * p.w;
    }

    // direct column reduction into the output (REDG, no return value)
    atomicAdd(&obj[col0 + 0], o0);
    atomicAdd(&obj[col0 + 1], o1);
    atomicAdd(&obj[col0 + 2], o2);
    atomicAdd(&obj[col0 + 3], o3);
}

extern "C" void kernel_launch(void* const* d_in, const int* in_sizes, int n_in,
                              void* d_out, int out_size) {
    const float* logp   = (const float*)d_in[0];  // log_probs  [B,T]
    const float* logits = (const float*)d_in[1];  // logits     [B,T,1]
    const float* weight = (const float*)d_in[2];  // weight     [B,T]
    const float* base   = (const float*)d_in[3];  // baselines  [B,T,1]
    float* out = (float*)d_out;

    phaseA_kernel<<<NPA, TPB>>>(logits, weight, base, out + Tn, out);
    reduce_mean_kernel<<<Tn / 32, 512>>>();
    phaseB_kernel<<<NPB, TPB>>>(out + Tn, base, logp, out);
}